// round 16
// baseline (speedup 1.0000x reference)
#include <cuda_runtime.h>
#include <cuda_fp16.h>
#include <cstdint>

#define NBATCH 8
#define NTOK   4096
#define DDIM   256
#define BM     64
#define BN     64
#define NITER  (NTOK / BN)   // 64
#define KP     264   // Q/K row pitch (halfs)
#define VP     72    // V row pitch (halfs)
#define PP     72    // P row pitch (halfs)
#define XPK    136   // proj X tile pitch (halfs)
#define WPK    40    // proj W tile pitch (halfs)

// fp16 scratch: Q,K token-major [b][tok][d]; V transposed [b][d][tok].
// Q pre-scaled by log2(e)/sqrt(256) so attention uses bare ex2.
__device__ __half g_qh [(size_t)NBATCH * NTOK * DDIM];
__device__ __half g_kh [(size_t)NBATCH * NTOK * DDIM];
__device__ __half g_vTh[(size_t)NBATCH * DDIM * NTOK];

// ---------- helpers ----------
__device__ __forceinline__ unsigned h2u(__half2 h) {
    union { __half2 h; unsigned u; } cvt;
    cvt.h = h;
    return cvt.u;
}
__device__ __forceinline__ float ex2f(float x) {
    float r; asm("ex2.approx.f32 %0, %1;" : "=f"(r) : "f"(x)); return r;
}

__device__ __forceinline__ void ldsm4(unsigned& r0, unsigned& r1, unsigned& r2,
                                      unsigned& r3, const __half* p) {
    unsigned a = (unsigned)__cvta_generic_to_shared(p);
    asm volatile("ldmatrix.sync.aligned.m8n8.x4.shared.b16 {%0,%1,%2,%3}, [%4];"
                 : "=r"(r0), "=r"(r1), "=r"(r2), "=r"(r3) : "r"(a));
}
__device__ __forceinline__ void ldsm4t(unsigned& r0, unsigned& r1, unsigned& r2,
                                       unsigned& r3, const __half* p) {
    unsigned a = (unsigned)__cvta_generic_to_shared(p);
    asm volatile("ldmatrix.sync.aligned.m8n8.x4.trans.shared.b16 {%0,%1,%2,%3}, [%4];"
                 : "=r"(r0), "=r"(r1), "=r"(r2), "=r"(r3) : "r"(a));
}
__device__ __forceinline__ void stsm4(__half* p, unsigned r0, unsigned r1,
                                      unsigned r2, unsigned r3) {
    unsigned a = (unsigned)__cvta_generic_to_shared(p);
    asm volatile("stmatrix.sync.aligned.m8n8.x4.shared.b16 [%0], {%1,%2,%3,%4};"
                 :: "r"(a), "r"(r0), "r"(r1), "r"(r2), "r"(r3) : "memory");
}

__device__ __forceinline__ void mma_f16(float* c, unsigned a0, unsigned a1, unsigned a2,
                                        unsigned a3, unsigned b0, unsigned b1) {
    asm volatile(
        "mma.sync.aligned.m16n8k16.row.col.f32.f16.f16.f32 "
        "{%0,%1,%2,%3},{%4,%5,%6,%7},{%8,%9},{%0,%1,%2,%3};\n"
        : "+f"(c[0]), "+f"(c[1]), "+f"(c[2]), "+f"(c[3])
        : "r"(a0), "r"(a1), "r"(a2), "r"(a3), "r"(b0), "r"(b1));
}

__device__ __forceinline__ void cp16(void* dst, const void* src) {
    unsigned d = (unsigned)__cvta_generic_to_shared(dst);
    asm volatile("cp.async.cg.shared.global [%0], [%1], 16;" :: "r"(d), "l"(src));
}
#define CP_COMMIT() asm volatile("cp.async.commit_group;" ::: "memory")
#define CP_WAIT1()  asm volatile("cp.async.wait_group 1;" ::: "memory")
#define BAR(id)      asm volatile("bar.sync %0, 256;"   :: "r"(id) : "memory")
#define BAR_ARR(id)  asm volatile("bar.arrive %0, 512;" :: "r"(id) : "memory")
#define BAR_WAIT(id) asm volatile("bar.sync %0, 512;"   :: "r"(id) : "memory")

// ============================================================================
// Kernel 1: FUSED QKV projection, fp16 mma, SOFTWARE-PIPELINED global loads:
// chunk k+1's X/W LDGs issue right after the STS barrier, overlapping the
// mma of chunk k. X staged k-major (A via ldmatrix.trans), W k-contiguous.
// ============================================================================
__global__ __launch_bounds__(256) void qkv_proj_kernel(
    const float* __restrict__ x, const float* __restrict__ Wq,
    const float* __restrict__ Wk, const float* __restrict__ Wv)
{
    __shared__ __half Xs[32][XPK];
    __shared__ __half Ws[3][64][WPK];

    const int batch = blockIdx.z;
    const int n0    = blockIdx.x * 128;
    const int d0    = blockIdx.y * 64;

    const int tid = threadIdx.x, warp = tid >> 5, lane = tid & 31;
    const int g = lane >> 2, t = lane & 3;
    const int lgrp = lane >> 3, lrow = lane & 7;
    const int m0 = warp * 16;

    float acc[3][8][4];
#pragma unroll
    for (int m = 0; m < 3; m++)
#pragma unroll
        for (int nf = 0; nf < 8; nf++)
#pragma unroll
            for (int i = 0; i < 4; i++) acc[m][nf][i] = 0.f;

    // register staging for the current chunk's tiles
    float4 xr[4];
    float4 wr[3][2];

    // load chunk 0 into regs
#pragma unroll
    for (int ii = 0; ii < 4; ii++) {
        int i = tid + ii * 256, r = i >> 5, cq = i & 31;
        xr[ii] = *(const float4*)(x + ((size_t)(batch * 256 + r)) * 4096 + n0 + cq * 4);
    }
#pragma unroll
    for (int m = 0; m < 3; m++) {
        const float* W = (m == 0) ? Wq : ((m == 1) ? Wk : Wv);
#pragma unroll
        for (int ii = 0; ii < 2; ii++) {
            int i = tid + ii * 256, r = i >> 3, cq = i & 7;
            wr[m][ii] = *(const float4*)(W + (size_t)(d0 + r) * 256 + cq * 4);
        }
    }

    for (int kc = 0; kc < 256; kc += 32) {
        // store current regs to smem (fp16 convert)
#pragma unroll
        for (int ii = 0; ii < 4; ii++) {
            int i = tid + ii * 256, r = i >> 5, cq = i & 31;
            *(__half2*)&Xs[r][cq * 4]     = __floats2half2_rn(xr[ii].x, xr[ii].y);
            *(__half2*)&Xs[r][cq * 4 + 2] = __floats2half2_rn(xr[ii].z, xr[ii].w);
        }
#pragma unroll
        for (int m = 0; m < 3; m++)
#pragma unroll
            for (int ii = 0; ii < 2; ii++) {
                int i = tid + ii * 256, r = i >> 3, cq = i & 7;
                *(__half2*)&Ws[m][r][cq * 4]     = __floats2half2_rn(wr[m][ii].x, wr[m][ii].y);
                *(__half2*)&Ws[m][r][cq * 4 + 2] = __floats2half2_rn(wr[m][ii].z, wr[m][ii].w);
            }
        __syncthreads();

        // issue next chunk's LDGs (overlap with mma below)
        if (kc + 32 < 256) {
#pragma unroll
            for (int ii = 0; ii < 4; ii++) {
                int i = tid + ii * 256, r = i >> 5, cq = i & 31;
                xr[ii] = *(const float4*)(x + ((size_t)(batch * 256 + kc + 32 + r)) * 4096
                                          + n0 + cq * 4);
            }
#pragma unroll
            for (int m = 0; m < 3; m++) {
                const float* W = (m == 0) ? Wq : ((m == 1) ? Wk : Wv);
#pragma unroll
                for (int ii = 0; ii < 2; ii++) {
                    int i = tid + ii * 256, r = i >> 3, cq = i & 7;
                    wr[m][ii] = *(const float4*)(W + (size_t)(d0 + r) * 256 + kc + 32 + cq * 4);
                }
            }
        }

        // A-frags via ldsm.trans: stored (k rows, m cols) -> logical (m, k)
        unsigned A[2][4];
        const __half* ap = &Xs[(lgrp >> 1) * 8 + lrow][m0 + (lgrp & 1) * 8];
        ldsm4t(A[0][0], A[0][1], A[0][2], A[0][3], ap);
        ldsm4t(A[1][0], A[1][1], A[1][2], A[1][3], ap + 16 * XPK);

#pragma unroll
        for (int m = 0; m < 3; m++)
#pragma unroll
            for (int nfp = 0; nfp < 4; nfp++)
#pragma unroll
                for (int ks = 0; ks < 2; ks++) {
                    unsigned b0, b1, b2, b3;
                    ldsm4(b0, b1, b2, b3,
                          &Ws[m][nfp * 16 + (lgrp >> 1) * 8 + lrow][(lgrp & 1) * 8 + ks * 16]);
                    mma_f16(acc[m][nfp * 2],
                            A[ks][0], A[ks][1], A[ks][2], A[ks][3], b0, b1);
                    mma_f16(acc[m][nfp * 2 + 1],
                            A[ks][0], A[ks][1], A[ks][2], A[ks][3], b2, b3);
                }
        __syncthreads();
    }

    // Q scale folds 1/16 and log2(e): attention uses bare ex2.
    const float QSC = 0.0625f * 1.4426950408889634f;
    {
        __half* qb = g_qh + ((size_t)batch * NTOK + n0 + m0) * DDIM + d0;
        __half* kb = g_kh + ((size_t)batch * NTOK + n0 + m0) * DDIM + d0;
#pragma unroll
        for (int nf = 0; nf < 8; nf++) {
            int d = nf * 8 + 2 * t;
            *(__half2*)(qb + (size_t)g * DDIM + d) =
                __floats2half2_rn(acc[0][nf][0] * QSC, acc[0][nf][1] * QSC);
            *(__half2*)(qb + (size_t)(g + 8) * DDIM + d) =
                __floats2half2_rn(acc[0][nf][2] * QSC, acc[0][nf][3] * QSC);
            *(__half2*)(kb + (size_t)g * DDIM + d) =
                __floats2half2_rn(acc[1][nf][0], acc[1][nf][1]);
            *(__half2*)(kb + (size_t)(g + 8) * DDIM + d) =
                __floats2half2_rn(acc[1][nf][2], acc[1][nf][3]);
        }
    }
    {
        __half* vb = g_vTh + (size_t)batch * DDIM * NTOK;
        int tok0 = n0 + m0;
#pragma unroll
        for (int nf = 0; nf < 8; nf++) {
            int d = d0 + nf * 8 + 2 * t;
            vb[(size_t)d * NTOK + tok0 + g]           = __float2half_rn(acc[2][nf][0]);
            vb[(size_t)(d + 1) * NTOK + tok0 + g]     = __float2half_rn(acc[2][nf][1]);
            vb[(size_t)d * NTOK + tok0 + 8 + g]       = __float2half_rn(acc[2][nf][2]);
            vb[(size_t)(d + 1) * NTOK + tok0 + 8 + g] = __float2half_rn(acc[2][nf][3]);
        }
    }
}

// ============================================================================
// Kernel 2: decoupled warp-specialized flash attention, lag-2, 4 P buffers,
// per-slot named barriers. R14 ordering restored (P publish BEFORE prefetch);
// softmax via bare ex2 (log2e pre-folded into Q).
// ============================================================================
#define SH_Q   0
#define SH_K   16896                     // 64*264
#define SH_V   (SH_K + 2 * BN * KP)      // 50688
#define SH_P   (SH_V + 2 * 256 * VP)     // 87552
#define SH_END (SH_P + 4 * BM * PP)      // 105984 halfs
#define ATTN_SMEM_BYTES (SH_END * 2 + 128 * 4)

__global__ __launch_bounds__(512) void attn_kernel(float* __restrict__ out)
{
    extern __shared__ __align__(16) __half smh[];
    __half* Qs = smh + SH_Q;
    __half* Ks = smh + SH_K;
    __half* Vs = smh + SH_V;
    __half* Ps = smh + SH_P;
    float* row_l2 = (float*)(smh + SH_END);

    const int batch = blockIdx.y;
    const int m0g   = blockIdx.x * BM;
    const int tid = threadIdx.x, warp = tid >> 5, lane = tid & 31;
    const int g = lane >> 2, t = lane & 3;
    const int lt = tid & 255;
    const int lgrp = lane >> 3, lrow = lane & 7;

    const __half* Qg  = g_qh  + ((size_t)batch * NTOK + m0g) * DDIM;
    const __half* Kg  = g_kh  + (size_t)batch * NTOK * DDIM;
    const __half* VgT = g_vTh + (size_t)batch * DDIM * NTOK;

    // ---- initial cp.async ----
    if (tid < 256) {
#pragma unroll
        for (int ii = 0; ii < 8; ii++) {
            int i = lt + ii * 256, r = i >> 5, c = i & 31;
            cp16(Qs + r * KP + c * 8, Qg + (size_t)r * DDIM + c * 8);
        }
#pragma unroll
        for (int ii = 0; ii < 8; ii++) {
            int i = lt + ii * 256, r = i >> 5, c = i & 31;
            cp16(Ks + r * KP + c * 8, Kg + (size_t)r * DDIM + c * 8);
        }
        CP_COMMIT();
#pragma unroll
        for (int ii = 0; ii < 8; ii++) {
            int i = lt + ii * 256, r = i >> 5, c = i & 31;
            cp16(Ks + BN * KP + r * KP + c * 8, Kg + (size_t)(BN + r) * DDIM + c * 8);
        }
        CP_COMMIT();
    } else {
#pragma unroll
        for (int ii = 0; ii < 8; ii++) {
            int i = lt + ii * 256, r = i >> 3, c = i & 7;
            cp16(Vs + r * VP + c * 8, VgT + (size_t)r * NTOK + c * 8);
        }
        CP_COMMIT();
#pragma unroll
        for (int ii = 0; ii < 8; ii++) {
            int i = lt + ii * 256, r = i >> 3, c = i & 7;
            cp16(Vs + 256 * VP + r * VP + c * 8, VgT + (size_t)r * NTOK + BN + c * 8);
        }
        CP_COMMIT();
    }

    const int wm = warp >> 1, wn = warp & 1;     // S-half: 16x32 tiles
    const int dw = (warp - 8) * 32;              // PV-half d slice
    float sum0 = 0.f, sum1 = 0.f;

    // Union register file: S-half = Q fragments, PV-half = O accumulators.
    float fr[64];
#pragma unroll
    for (int i = 0; i < 64; i++) fr[i] = 0.f;

    // S active for j in [0,NITER); PV active for j in [2,NITER+2), i0 = j-2.
    for (int j = 0; j < NITER + 2; j++) {
        if (tid < 256) {
            if (j < NITER) {
                if (j >= 4) BAR_WAIT(7 + (j & 3));   // P buf (j&3) freed by PV @ i0=j-4
                CP_WAIT1();                           // K_j (and Q on j=0) arrived
                BAR(1);

                if (j == 0) {
                    const __half* qp = Qs + (wm * 16 + (lgrp & 1) * 8 + lrow) * KP
                                          + (lgrp >> 1) * 8;
#pragma unroll
                    for (int s = 0; s < 16; s++) {
                        unsigned a0, a1, a2, a3;
                        ldsm4(a0, a1, a2, a3, qp + s * 16);
                        fr[s * 4 + 0] = __uint_as_float(a0);
                        fr[s * 4 + 1] = __uint_as_float(a1);
                        fr[s * 4 + 2] = __uint_as_float(a2);
                        fr[s * 4 + 3] = __uint_as_float(a3);
                    }
                }

                const __half* Kb = Ks + (j & 1) * BN * KP;
                const __half* kp = Kb + (wn * 32 + (lgrp >> 1) * 8 + lrow) * KP
                                      + (lgrp & 1) * 8;

                float s2[4][4];
#pragma unroll
                for (int nf = 0; nf < 4; nf++)
#pragma unroll
                    for (int i = 0; i < 4; i++) s2[nf][i] = 0.f;

#pragma unroll
                for (int s = 0; s < 16; s++) {
                    unsigned a0 = __float_as_uint(fr[s * 4 + 0]);
                    unsigned a1 = __float_as_uint(fr[s * 4 + 1]);
                    unsigned a2 = __float_as_uint(fr[s * 4 + 2]);
                    unsigned a3 = __float_as_uint(fr[s * 4 + 3]);
                    unsigned b0, b1, b2, b3;
                    ldsm4(b0, b1, b2, b3, kp + s * 16);
                    mma_f16(s2[0], a0, a1, a2, a3, b0, b1);
                    mma_f16(s2[1], a0, a1, a2, a3, b2, b3);
                    ldsm4(b0, b1, b2, b3, kp + 16 * KP + s * 16);
                    mma_f16(s2[2], a0, a1, a2, a3, b0, b1);
                    mma_f16(s2[3], a0, a1, a2, a3, b2, b3);
                }

                // softmax via ex2, row sums, P store via STSM into buf j&3
                __half* Pb = Ps + (j & 3) * BM * PP;
                unsigned up[4], lo[4];
#pragma unroll
                for (int nf = 0; nf < 4; nf++) {
                    float p0 = ex2f(s2[nf][0]), p1 = ex2f(s2[nf][1]);
                    float p2 = ex2f(s2[nf][2]), p3 = ex2f(s2[nf][3]);
                    sum0 += p0 + p1;
                    sum1 += p2 + p3;
                    up[nf] = h2u(__floats2half2_rn(p0, p1));
                    lo[nf] = h2u(__floats2half2_rn(p2, p3));
                }
                __half* sp = Pb + (wm * 16 + ((lgrp & 1) << 3) + lrow) * PP
                                + wn * 32 + (lgrp >> 1) * 8;
                stsm4(sp,      up[0], lo[0], up[1], lo[1]);
                stsm4(sp + 16, up[2], lo[2], up[3], lo[3]);

                BAR_ARR(3 + (j & 3));                 // P_j published

                BAR(1);                               // S-half done with K buf j&1
                if (j + 2 < NITER) {
                    __half* Kd = Ks + (j & 1) * BN * KP;
                    const __half* Kgs = Kg + (size_t)(j + 2) * BN * DDIM;
#pragma unroll
                    for (int ii = 0; ii < 8; ii++) {
                        int i = lt + ii * 256, r = i >> 5, c = i & 31;
                        cp16(Kd + r * KP + c * 8, Kgs + (size_t)r * DDIM + c * 8);
                    }
                }
                CP_COMMIT();
            }
        } else {
            if (j >= 2) {
                const int i0 = j - 2;                 // tile being consumed
                CP_WAIT1();                           // V_{i0} arrived
                BAR(2);
                BAR_WAIT(3 + (i0 & 3));               // P_{i0} published

                const __half* Vb = Vs + (i0 & 1) * 256 * VP;
                const __half* Pb = Ps + (i0 & 3) * BM * PP;
                const __half* pp = Pb + ((lgrp & 1) * 8 + lrow) * PP + (lgrp >> 1) * 8;
                const __half* vp = Vb + (dw + (lgrp >> 1) * 8 + lrow) * VP + (lgrp & 1) * 8;

#pragma unroll
                for (int ks = 0; ks < 4; ks++) {
                    unsigned b0r[4], b1r[4];
                    ldsm4(b0r[0], b1r[0], b0r[1], b1r[1], vp + ks * 16);
                    ldsm4(b0r[2], b1r[2], b0r[3], b1r[3], vp + 16 * VP + ks * 16);
#pragma unroll
                    for (int mt = 0; mt < 4; mt++) {
                        unsigned a0, a1, a2, a3;
                        ldsm4(a0, a1, a2, a3, pp + mt * 16 * PP + ks * 16);
#pragma unroll
                        for (int nf = 0; nf < 4; nf++)
                            mma_f16(&fr[(mt * 4 + nf) * 4], a0, a1, a2, a3, b0r[nf], b1r[nf]);
                    }
                }

                BAR_ARR(7 + (i0 & 3));                // P buf (i0&3) free

                BAR(2);                               // PV-half done with V buf i0&1
                if (i0 + 2 < NITER) {
                    __half* Vd = Vs + (i0 & 1) * 256 * VP;
                    const __half* Vgs = VgT + (size_t)(i0 + 2) * BN;
#pragma unroll
                    for (int ii = 0; ii < 8; ii++) {
                        int ix = lt + ii * 256, r = ix >> 3, c = ix & 7;
                        cp16(Vd + r * VP + c * 8, Vgs + (size_t)r * NTOK + c * 8);
                    }
                }
                CP_COMMIT();
            }
        }
    }

    // ---- row-sum reduction (S-half) ----
    if (tid < 256) {
        sum0 += __shfl_xor_sync(0xffffffffu, sum0, 1);
        sum0 += __shfl_xor_sync(0xffffffffu, sum0, 2);
        sum1 += __shfl_xor_sync(0xffffffffu, sum1, 1);
        sum1 += __shfl_xor_sync(0xffffffffu, sum1, 2);
        if (t == 0) {
            row_l2[wn * 64 + wm * 16 + g]     = sum0;
            row_l2[wn * 64 + wm * 16 + 8 + g] = sum1;
        }
    }
    __syncthreads();

    // ---- epilogue: out[b][d][token] = O / l  (PV-half) ----
    if (tid >= 256) {
#pragma unroll
        for (int mt = 0; mt < 4; mt++) {
            int r0 = mt * 16 + g, r1 = r0 + 8;
            float il0 = 1.f / (row_l2[r0] + row_l2[64 + r0]);
            float il1 = 1.f / (row_l2[r1] + row_l2[64 + r1]);
#pragma unroll
            for (int nf = 0; nf < 4; nf++) {
                int d = dw + nf * 8 + 2 * t;
                size_t base = ((size_t)batch * DDIM + d) * NTOK + m0g;
                float* o4 = &fr[(mt * 4 + nf) * 4];
                out[base + r0]        = o4[0] * il0;
                out[base + NTOK + r0] = o4[1] * il0;
                out[base + r1]        = o4[2] * il1;
                out[base + NTOK + r1] = o4[3] * il1;
            }
        }
    }
}

extern "C" void kernel_launch(void* const* d_in, const int* in_sizes, int n_in,
                              void* d_out, int out_size) {
    const float* x  = (const float*)d_in[0];
    const float* Wq = (const float*)d_in[1];
    const float* Wk = (const float*)d_in[2];
    const float* Wv = (const float*)d_in[3];
    float* out = (float*)d_out;

    dim3 gp(NTOK / 128, 4, NBATCH);
    qkv_proj_kernel<<<gp, 256>>>(x, Wq, Wk, Wv);

    cudaFuncSetAttribute(attn_kernel, cudaFuncAttributeMaxDynamicSharedMemorySize,
                         ATTN_SMEM_BYTES);
    dim3 ga(NTOK / BM, NBATCH);
    attn_kernel<<<ga, 512, ATTN_SMEM_BYTES>>>(out);
}

// round 17
// speedup vs baseline: 1.7597x; 1.7597x over previous
#include <cuda_runtime.h>
#include <cuda_fp16.h>
#include <cstdint>

#define NBATCH 8
#define NTOK   4096
#define DDIM   256
#define BM     64
#define BN     64
#define NITER  (NTOK / BN)   // 64
#define KP     264   // Q/K row pitch (halfs)
#define VP     72    // V row pitch (halfs)
#define PP     72    // P row pitch (halfs)
#define XPK    136   // proj X tile pitch (halfs)
#define WPK    40    // proj W tile pitch (halfs)

// fp16 scratch: Q,K token-major [b][tok][d]; V transposed [b][d][tok].
// Q pre-scaled by 1/sqrt(256) = 1/16.
__device__ __half g_qh [(size_t)NBATCH * NTOK * DDIM];
__device__ __half g_kh [(size_t)NBATCH * NTOK * DDIM];
__device__ __half g_vTh[(size_t)NBATCH * DDIM * NTOK];

// ---------- helpers ----------
__device__ __forceinline__ unsigned h2u(__half2 h) {
    union { __half2 h; unsigned u; } cvt;
    cvt.h = h;
    return cvt.u;
}

__device__ __forceinline__ void ldsm4(unsigned& r0, unsigned& r1, unsigned& r2,
                                      unsigned& r3, const __half* p) {
    unsigned a = (unsigned)__cvta_generic_to_shared(p);
    asm volatile("ldmatrix.sync.aligned.m8n8.x4.shared.b16 {%0,%1,%2,%3}, [%4];"
                 : "=r"(r0), "=r"(r1), "=r"(r2), "=r"(r3) : "r"(a));
}
__device__ __forceinline__ void ldsm4t(unsigned& r0, unsigned& r1, unsigned& r2,
                                       unsigned& r3, const __half* p) {
    unsigned a = (unsigned)__cvta_generic_to_shared(p);
    asm volatile("ldmatrix.sync.aligned.m8n8.x4.trans.shared.b16 {%0,%1,%2,%3}, [%4];"
                 : "=r"(r0), "=r"(r1), "=r"(r2), "=r"(r3) : "r"(a));
}
__device__ __forceinline__ void stsm4(__half* p, unsigned r0, unsigned r1,
                                      unsigned r2, unsigned r3) {
    unsigned a = (unsigned)__cvta_generic_to_shared(p);
    asm volatile("stmatrix.sync.aligned.m8n8.x4.shared.b16 [%0], {%1,%2,%3,%4};"
                 :: "r"(a), "r"(r0), "r"(r1), "r"(r2), "r"(r3) : "memory");
}

__device__ __forceinline__ void mma_f16(float* c, unsigned a0, unsigned a1, unsigned a2,
                                        unsigned a3, unsigned b0, unsigned b1) {
    asm volatile(
        "mma.sync.aligned.m16n8k16.row.col.f32.f16.f16.f32 "
        "{%0,%1,%2,%3},{%4,%5,%6,%7},{%8,%9},{%0,%1,%2,%3};\n"
        : "+f"(c[0]), "+f"(c[1]), "+f"(c[2]), "+f"(c[3])
        : "r"(a0), "r"(a1), "r"(a2), "r"(a3), "r"(b0), "r"(b1));
}

__device__ __forceinline__ void cp16(void* dst, const void* src) {
    unsigned d = (unsigned)__cvta_generic_to_shared(dst);
    asm volatile("cp.async.cg.shared.global [%0], [%1], 16;" :: "r"(d), "l"(src));
}
#define CP_COMMIT() asm volatile("cp.async.commit_group;" ::: "memory")
#define CP_WAIT1()  asm volatile("cp.async.wait_group 1;" ::: "memory")
#define BAR(id)      asm volatile("bar.sync %0, 256;"   :: "r"(id) : "memory")
#define BAR_ARR(id)  asm volatile("bar.arrive %0, 512;" :: "r"(id) : "memory")
#define BAR_WAIT(id) asm volatile("bar.sync %0, 512;"   :: "r"(id) : "memory")

// ============================================================================
// Kernel 1: FUSED QKV projection, fp16 mma, software-pipelined global loads.
// ============================================================================
__global__ __launch_bounds__(256) void qkv_proj_kernel(
    const float* __restrict__ x, const float* __restrict__ Wq,
    const float* __restrict__ Wk, const float* __restrict__ Wv)
{
    __shared__ __half Xs[32][XPK];
    __shared__ __half Ws[3][64][WPK];

    const int batch = blockIdx.z;
    const int n0    = blockIdx.x * 128;
    const int d0    = blockIdx.y * 64;

    const int tid = threadIdx.x, warp = tid >> 5, lane = tid & 31;
    const int g = lane >> 2, t = lane & 3;
    const int lgrp = lane >> 3, lrow = lane & 7;
    const int m0 = warp * 16;

    float acc[3][8][4];
#pragma unroll
    for (int m = 0; m < 3; m++)
#pragma unroll
        for (int nf = 0; nf < 8; nf++)
#pragma unroll
            for (int i = 0; i < 4; i++) acc[m][nf][i] = 0.f;

    float4 xr[4];
    float4 wr[3][2];

#pragma unroll
    for (int ii = 0; ii < 4; ii++) {
        int i = tid + ii * 256, r = i >> 5, cq = i & 31;
        xr[ii] = *(const float4*)(x + ((size_t)(batch * 256 + r)) * 4096 + n0 + cq * 4);
    }
#pragma unroll
    for (int m = 0; m < 3; m++) {
        const float* W = (m == 0) ? Wq : ((m == 1) ? Wk : Wv);
#pragma unroll
        for (int ii = 0; ii < 2; ii++) {
            int i = tid + ii * 256, r = i >> 3, cq = i & 7;
            wr[m][ii] = *(const float4*)(W + (size_t)(d0 + r) * 256 + cq * 4);
        }
    }

    for (int kc = 0; kc < 256; kc += 32) {
#pragma unroll
        for (int ii = 0; ii < 4; ii++) {
            int i = tid + ii * 256, r = i >> 5, cq = i & 31;
            *(__half2*)&Xs[r][cq * 4]     = __floats2half2_rn(xr[ii].x, xr[ii].y);
            *(__half2*)&Xs[r][cq * 4 + 2] = __floats2half2_rn(xr[ii].z, xr[ii].w);
        }
#pragma unroll
        for (int m = 0; m < 3; m++)
#pragma unroll
            for (int ii = 0; ii < 2; ii++) {
                int i = tid + ii * 256, r = i >> 3, cq = i & 7;
                *(__half2*)&Ws[m][r][cq * 4]     = __floats2half2_rn(wr[m][ii].x, wr[m][ii].y);
                *(__half2*)&Ws[m][r][cq * 4 + 2] = __floats2half2_rn(wr[m][ii].z, wr[m][ii].w);
            }
        __syncthreads();

        if (kc + 32 < 256) {
#pragma unroll
            for (int ii = 0; ii < 4; ii++) {
                int i = tid + ii * 256, r = i >> 5, cq = i & 31;
                xr[ii] = *(const float4*)(x + ((size_t)(batch * 256 + kc + 32 + r)) * 4096
                                          + n0 + cq * 4);
            }
#pragma unroll
            for (int m = 0; m < 3; m++) {
                const float* W = (m == 0) ? Wq : ((m == 1) ? Wk : Wv);
#pragma unroll
                for (int ii = 0; ii < 2; ii++) {
                    int i = tid + ii * 256, r = i >> 3, cq = i & 7;
                    wr[m][ii] = *(const float4*)(W + (size_t)(d0 + r) * 256 + kc + 32 + cq * 4);
                }
            }
        }

        unsigned A[2][4];
        const __half* ap = &Xs[(lgrp >> 1) * 8 + lrow][m0 + (lgrp & 1) * 8];
        ldsm4t(A[0][0], A[0][1], A[0][2], A[0][3], ap);
        ldsm4t(A[1][0], A[1][1], A[1][2], A[1][3], ap + 16 * XPK);

#pragma unroll
        for (int m = 0; m < 3; m++)
#pragma unroll
            for (int nfp = 0; nfp < 4; nfp++)
#pragma unroll
                for (int ks = 0; ks < 2; ks++) {
                    unsigned b0, b1, b2, b3;
                    ldsm4(b0, b1, b2, b3,
                          &Ws[m][nfp * 16 + (lgrp >> 1) * 8 + lrow][(lgrp & 1) * 8 + ks * 16]);
                    mma_f16(acc[m][nfp * 2],
                            A[ks][0], A[ks][1], A[ks][2], A[ks][3], b0, b1);
                    mma_f16(acc[m][nfp * 2 + 1],
                            A[ks][0], A[ks][1], A[ks][2], A[ks][3], b2, b3);
                }
        __syncthreads();
    }

    const float QSC = 0.0625f;
    {
        __half* qb = g_qh + ((size_t)batch * NTOK + n0 + m0) * DDIM + d0;
        __half* kb = g_kh + ((size_t)batch * NTOK + n0 + m0) * DDIM + d0;
#pragma unroll
        for (int nf = 0; nf < 8; nf++) {
            int d = nf * 8 + 2 * t;
            *(__half2*)(qb + (size_t)g * DDIM + d) =
                __floats2half2_rn(acc[0][nf][0] * QSC, acc[0][nf][1] * QSC);
            *(__half2*)(qb + (size_t)(g + 8) * DDIM + d) =
                __floats2half2_rn(acc[0][nf][2] * QSC, acc[0][nf][3] * QSC);
            *(__half2*)(kb + (size_t)g * DDIM + d) =
                __floats2half2_rn(acc[1][nf][0], acc[1][nf][1]);
            *(__half2*)(kb + (size_t)(g + 8) * DDIM + d) =
                __floats2half2_rn(acc[1][nf][2], acc[1][nf][3]);
        }
    }
    {
        __half* vb = g_vTh + (size_t)batch * DDIM * NTOK;
        int tok0 = n0 + m0;
#pragma unroll
        for (int nf = 0; nf < 8; nf++) {
            int d = d0 + nf * 8 + 2 * t;
            vb[(size_t)d * NTOK + tok0 + g]           = __float2half_rn(acc[2][nf][0]);
            vb[(size_t)(d + 1) * NTOK + tok0 + g]     = __float2half_rn(acc[2][nf][1]);
            vb[(size_t)d * NTOK + tok0 + 8 + g]       = __float2half_rn(acc[2][nf][2]);
            vb[(size_t)(d + 1) * NTOK + tok0 + 8 + g] = __float2half_rn(acc[2][nf][3]);
        }
    }
}

// ============================================================================
// Kernel 2: EXACT R14 attention — decoupled lag-2, 4 P buffers, per-slot
// named barriers, __expf softmax, publish-before-prefetch ordering.
// ============================================================================
#define SH_Q   0
#define SH_K   16896                     // 64*264
#define SH_V   (SH_K + 2 * BN * KP)      // 50688
#define SH_P   (SH_V + 2 * 256 * VP)     // 87552
#define SH_END (SH_P + 4 * BM * PP)      // 105984 halfs
#define ATTN_SMEM_BYTES (SH_END * 2 + 128 * 4)

__global__ __launch_bounds__(512) void attn_kernel(float* __restrict__ out)
{
    extern __shared__ __align__(16) __half smh[];
    __half* Qs = smh + SH_Q;
    __half* Ks = smh + SH_K;
    __half* Vs = smh + SH_V;
    __half* Ps = smh + SH_P;
    float* row_l2 = (float*)(smh + SH_END);

    const int batch = blockIdx.y;
    const int m0g   = blockIdx.x * BM;
    const int tid = threadIdx.x, warp = tid >> 5, lane = tid & 31;
    const int g = lane >> 2, t = lane & 3;
    const int lt = tid & 255;
    const int lgrp = lane >> 3, lrow = lane & 7;

    const __half* Qg  = g_qh  + ((size_t)batch * NTOK + m0g) * DDIM;
    const __half* Kg  = g_kh  + (size_t)batch * NTOK * DDIM;
    const __half* VgT = g_vTh + (size_t)batch * DDIM * NTOK;

    if (tid < 256) {
#pragma unroll
        for (int ii = 0; ii < 8; ii++) {
            int i = lt + ii * 256, r = i >> 5, c = i & 31;
            cp16(Qs + r * KP + c * 8, Qg + (size_t)r * DDIM + c * 8);
        }
#pragma unroll
        for (int ii = 0; ii < 8; ii++) {
            int i = lt + ii * 256, r = i >> 5, c = i & 31;
            cp16(Ks + r * KP + c * 8, Kg + (size_t)r * DDIM + c * 8);
        }
        CP_COMMIT();
#pragma unroll
        for (int ii = 0; ii < 8; ii++) {
            int i = lt + ii * 256, r = i >> 5, c = i & 31;
            cp16(Ks + BN * KP + r * KP + c * 8, Kg + (size_t)(BN + r) * DDIM + c * 8);
        }
        CP_COMMIT();
    } else {
#pragma unroll
        for (int ii = 0; ii < 8; ii++) {
            int i = lt + ii * 256, r = i >> 3, c = i & 7;
            cp16(Vs + r * VP + c * 8, VgT + (size_t)r * NTOK + c * 8);
        }
        CP_COMMIT();
#pragma unroll
        for (int ii = 0; ii < 8; ii++) {
            int i = lt + ii * 256, r = i >> 3, c = i & 7;
            cp16(Vs + 256 * VP + r * VP + c * 8, VgT + (size_t)r * NTOK + BN + c * 8);
        }
        CP_COMMIT();
    }

    const int wm = warp >> 1, wn = warp & 1;
    const int dw = (warp - 8) * 32;
    float sum0 = 0.f, sum1 = 0.f;

    float fr[64];
#pragma unroll
    for (int i = 0; i < 64; i++) fr[i] = 0.f;

    for (int j = 0; j < NITER + 2; j++) {
        if (tid < 256) {
            if (j < NITER) {
                if (j >= 4) BAR_WAIT(7 + (j & 3));
                CP_WAIT1();
                BAR(1);

                if (j == 0) {
                    const __half* qp = Qs + (wm * 16 + (lgrp & 1) * 8 + lrow) * KP
                                          + (lgrp >> 1) * 8;
#pragma unroll
                    for (int s = 0; s < 16; s++) {
                        unsigned a0, a1, a2, a3;
                        ldsm4(a0, a1, a2, a3, qp + s * 16);
                        fr[s * 4 + 0] = __uint_as_float(a0);
                        fr[s * 4 + 1] = __uint_as_float(a1);
                        fr[s * 4 + 2] = __uint_as_float(a2);
                        fr[s * 4 + 3] = __uint_as_float(a3);
                    }
                }

                const __half* Kb = Ks + (j & 1) * BN * KP;
                const __half* kp = Kb + (wn * 32 + (lgrp >> 1) * 8 + lrow) * KP
                                      + (lgrp & 1) * 8;

                float s2[4][4];
#pragma unroll
                for (int nf = 0; nf < 4; nf++)
#pragma unroll
                    for (int i = 0; i < 4; i++) s2[nf][i] = 0.f;

#pragma unroll
                for (int s = 0; s < 16; s++) {
                    unsigned a0 = __float_as_uint(fr[s * 4 + 0]);
                    unsigned a1 = __float_as_uint(fr[s * 4 + 1]);
                    unsigned a2 = __float_as_uint(fr[s * 4 + 2]);
                    unsigned a3 = __float_as_uint(fr[s * 4 + 3]);
                    unsigned b0, b1, b2, b3;
                    ldsm4(b0, b1, b2, b3, kp + s * 16);
                    mma_f16(s2[0], a0, a1, a2, a3, b0, b1);
                    mma_f16(s2[1], a0, a1, a2, a3, b2, b3);
                    ldsm4(b0, b1, b2, b3, kp + 16 * KP + s * 16);
                    mma_f16(s2[2], a0, a1, a2, a3, b0, b1);
                    mma_f16(s2[3], a0, a1, a2, a3, b2, b3);
                }

                __half* Pb = Ps + (j & 3) * BM * PP;
                unsigned up[4], lo[4];
#pragma unroll
                for (int nf = 0; nf < 4; nf++) {
                    float p0 = __expf(s2[nf][0]), p1 = __expf(s2[nf][1]);
                    float p2 = __expf(s2[nf][2]), p3 = __expf(s2[nf][3]);
                    sum0 += p0 + p1;
                    sum1 += p2 + p3;
                    up[nf] = h2u(__floats2half2_rn(p0, p1));
                    lo[nf] = h2u(__floats2half2_rn(p2, p3));
                }
                __half* sp = Pb + (wm * 16 + ((lgrp & 1) << 3) + lrow) * PP
                                + wn * 32 + (lgrp >> 1) * 8;
                stsm4(sp,      up[0], lo[0], up[1], lo[1]);
                stsm4(sp + 16, up[2], lo[2], up[3], lo[3]);

                BAR_ARR(3 + (j & 3));

                BAR(1);
                if (j + 2 < NITER) {
                    __half* Kd = Ks + (j & 1) * BN * KP;
                    const __half* Kgs = Kg + (size_t)(j + 2) * BN * DDIM;
#pragma unroll
                    for (int ii = 0; ii < 8; ii++) {
                        int i = lt + ii * 256, r = i >> 5, c = i & 31;
                        cp16(Kd + r * KP + c * 8, Kgs + (size_t)r * DDIM + c * 8);
                    }
                }
                CP_COMMIT();
            }
        } else {
            if (j >= 2) {
                const int i0 = j - 2;
                CP_WAIT1();
                BAR(2);
                BAR_WAIT(3 + (i0 & 3));

                const __half* Vb = Vs + (i0 & 1) * 256 * VP;
                const __half* Pb = Ps + (i0 & 3) * BM * PP;
                const __half* pp = Pb + ((lgrp & 1) * 8 + lrow) * PP + (lgrp >> 1) * 8;
                const __half* vp = Vb + (dw + (lgrp >> 1) * 8 + lrow) * VP + (lgrp & 1) * 8;

#pragma unroll
                for (int ks = 0; ks < 4; ks++) {
                    unsigned b0r[4], b1r[4];
                    ldsm4(b0r[0], b1r[0], b0r[1], b1r[1], vp + ks * 16);
                    ldsm4(b0r[2], b1r[2], b0r[3], b1r[3], vp + 16 * VP + ks * 16);
#pragma unroll
                    for (int mt = 0; mt < 4; mt++) {
                        unsigned a0, a1, a2, a3;
                        ldsm4(a0, a1, a2, a3, pp + mt * 16 * PP + ks * 16);
#pragma unroll
                        for (int nf = 0; nf < 4; nf++)
                            mma_f16(&fr[(mt * 4 + nf) * 4], a0, a1, a2, a3, b0r[nf], b1r[nf]);
                    }
                }

                BAR_ARR(7 + (i0 & 3));

                BAR(2);
                if (i0 + 2 < NITER) {
                    __half* Vd = Vs + (i0 & 1) * 256 * VP;
                    const __half* Vgs = VgT + (size_t)(i0 + 2) * BN;
#pragma unroll
                    for (int ii = 0; ii < 8; ii++) {
                        int ix = lt + ii * 256, r = ix >> 3, c = ix & 7;
                        cp16(Vd + r * VP + c * 8, Vgs + (size_t)r * NTOK + c * 8);
                    }
                }
                CP_COMMIT();
            }
        }
    }

    if (tid < 256) {
        sum0 += __shfl_xor_sync(0xffffffffu, sum0, 1);
        sum0 += __shfl_xor_sync(0xffffffffu, sum0, 2);
        sum1 += __shfl_xor_sync(0xffffffffu, sum1, 1);
        sum1 += __shfl_xor_sync(0xffffffffu, sum1, 2);
        if (t == 0) {
            row_l2[wn * 64 + wm * 16 + g]     = sum0;
            row_l2[wn * 64 + wm * 16 + 8 + g] = sum1;
        }
    }
    __syncthreads();

    if (tid >= 256) {
#pragma unroll
        for (int mt = 0; mt < 4; mt++) {
            int r0 = mt * 16 + g, r1 = r0 + 8;
            float il0 = 1.f / (row_l2[r0] + row_l2[64 + r0]);
            float il1 = 1.f / (row_l2[r1] + row_l2[64 + r1]);
#pragma unroll
            for (int nf = 0; nf < 4; nf++) {
                int d = dw + nf * 8 + 2 * t;
                size_t base = ((size_t)batch * DDIM + d) * NTOK + m0g;
                float* o4 = &fr[(mt * 4 + nf) * 4];
                out[base + r0]        = o4[0] * il0;
                out[base + NTOK + r0] = o4[1] * il0;
                out[base + r1]        = o4[2] * il1;
                out[base + NTOK + r1] = o4[3] * il1;
            }
        }
    }
}

extern "C" void kernel_launch(void* const* d_in, const int* in_sizes, int n_in,
                              void* d_out, int out_size) {
    const float* x  = (const float*)d_in[0];
    const float* Wq = (const float*)d_in[1];
    const float* Wk = (const float*)d_in[2];
    const float* Wv = (const float*)d_in[3];
    float* out = (float*)d_out;

    dim3 gp(NTOK / 128, 4, NBATCH);
    qkv_proj_kernel<<<gp, 256>>>(x, Wq, Wk, Wv);

    cudaFuncSetAttribute(attn_kernel, cudaFuncAttributeMaxDynamicSharedMemorySize,
                         ATTN_SMEM_BYTES);
    dim3 ga(NTOK / BM, NBATCH);
    attn_kernel<<<ga, 512, ATTN_SMEM_BYTES>>>(out);
}